// round 4
// baseline (speedup 1.0000x reference)
#include <cuda_runtime.h>
#include <math.h>

// Shapes (fixed by the problem)
#define B_  16
#define M_  1024
#define W_  256
#define H_  8
#define NW_ 2
#define NR_ 4
#define EPS 1e-6f

// Output layout: concatenation of the 6 returned tensors (float32)
#define O_UPD   0                               // [B,M,W]  4,194,304
#define O_COS   (O_UPD + B_*M_*W_)              // [B,H,M]    131,072
#define O_LINK  (O_COS + B_*H_*M_)              // [B,NW,M,M] 33,554,432
#define O_PREC  (O_LINK + B_*NW_*M_*M_)         // [B,NW,M]    32,768
#define O_USE   (O_PREC + B_*NW_*M_)            // [B,M]       16,384
#define O_READ  (O_USE + B_*M_)                 // [B,W]        4,096

// Tiny per-(b,h) precomputation scratch
__device__ float g_knorm[B_ * H_];
__device__ float g_softp[B_ * H_];

// ---------------------------------------------------------------------------
// Kernel 0: per-(b,h) key L2-norm and softplus(strength).  grid=128, block=256
// ---------------------------------------------------------------------------
__global__ void k_keyprep(const float* __restrict__ keys,
                          const float* __restrict__ strengths) {
    int bh = blockIdx.x;           // b*H + h
    int tid = threadIdx.x;         // 0..255 == w
    float v = keys[bh * W_ + tid];
    float s = v * v;
    // warp reduce
    #pragma unroll
    for (int off = 16; off > 0; off >>= 1)
        s += __shfl_down_sync(0xffffffffu, s, off);
    __shared__ float red[8];
    if ((tid & 31) == 0) red[tid >> 5] = s;
    __syncthreads();
    if (tid == 0) {
        float t = 0.f;
        #pragma unroll
        for (int i = 0; i < 8; i++) t += red[i];
        g_knorm[bh] = sqrtf(t + EPS);
        float st = strengths[bh];
        g_softp[bh] = log1pf(expf(st));   // softplus
    }
}

// ---------------------------------------------------------------------------
// Kernel 1 (the fused pass): one block per (b,m) row of memory.
//   grid = (M, B), block = 256 (= W)
//   - 8 key dot products + ||mem_row||^2  (9 block reductions)
//   - sharp scores -> cosine output region (softmax'd in-place later)
//   - erase/write -> updated_memory
//   - usage update (thread 0)
// ---------------------------------------------------------------------------
__global__ void __launch_bounds__(256)
k_fused(const float* __restrict__ memory,
        const float* __restrict__ keys,
        const float* __restrict__ write_weights,
        const float* __restrict__ free_gate,
        const float* __restrict__ read_weights,
        const float* __restrict__ prev_usage,
        const float* __restrict__ erase_vectors,
        const float* __restrict__ write_vectors,
        float* __restrict__ out) {
    const int m = blockIdx.x;
    const int b = blockIdx.y;
    const int tid = threadIdx.x;   // w index
    const int lane = tid & 31, warp = tid >> 5;

    __shared__ float skey[H_][W_];
    __shared__ float red[8][9];     // [warp][value]
    __shared__ float res[9];        // final reduced: 8 dots + sumsq

    // stage keys for this batch (stays L2-hot; 8 loads/thread)
    #pragma unroll
    for (int h = 0; h < H_; h++)
        skey[h][tid] = keys[(b * H_ + h) * W_ + tid];
    __syncthreads();

    const float mv = memory[((long)(b * M_ + m)) * W_ + tid];

    float acc[9];
    acc[8] = mv * mv;
    #pragma unroll
    for (int h = 0; h < H_; h++) acc[h] = mv * skey[h][tid];

    #pragma unroll
    for (int i = 0; i < 9; i++) {
        float s = acc[i];
        #pragma unroll
        for (int off = 16; off > 0; off >>= 1)
            s += __shfl_down_sync(0xffffffffu, s, off);
        if (lane == 0) red[warp][i] = s;
    }
    __syncthreads();
    if (tid < 9) {
        float s = 0.f;
        #pragma unroll
        for (int w8 = 0; w8 < 8; w8++) s += red[w8][tid];
        res[tid] = s;
    }
    __syncthreads();

    // sharp scores (pre-softmax) into cosine region
    if (tid < H_) {
        float memnorm = sqrtf(res[8] + EPS);
        float nd = res[tid] / (memnorm * g_knorm[b * H_ + tid] + EPS);
        out[O_COS + ((b * H_ + tid) * M_) + m] = nd * g_softp[b * H_ + tid];
    }

    // erase / write
    const float ww0 = write_weights[(b * NW_ + 0) * M_ + m];
    const float ww1 = write_weights[(b * NW_ + 1) * M_ + m];
    float e = ww0 * erase_vectors[(b * NW_ + 0) * W_ + tid]
            + ww1 * erase_vectors[(b * NW_ + 1) * W_ + tid];
    e = fminf(fmaxf(e, 0.f), 1.f);
    float wr = ww0 * write_vectors[(b * NW_ + 0) * W_ + tid]
             + ww1 * write_vectors[(b * NW_ + 1) * W_ + tid];
    out[O_UPD + ((long)(b * M_ + m)) * W_ + tid] = mv * (1.f - e) + wr;

    // usage
    if (tid == 0) {
        float u = prev_usage[b * M_ + m] + ww0 + ww1;
        #pragma unroll
        for (int r = 0; r < NR_; r++)
            u -= read_weights[(b * NR_ + r) * M_ + m] * free_gate[b * NR_ + r];
        out[O_USE + b * M_ + m] = fminf(fmaxf(u, 0.f), 1.f);
    }
}

// ---------------------------------------------------------------------------
// Kernel 2: in-place softmax over M for each (b,h).  grid=128, block=256
// ---------------------------------------------------------------------------
__global__ void __launch_bounds__(256)
k_softmax(float* __restrict__ out) {
    const int bh = blockIdx.x;
    const int tid = threadIdx.x;
    const int lane = tid & 31, warp = tid >> 5;
    float* row = out + O_COS + (long)bh * M_;

    float v[4];
    float mx = -INFINITY;
    #pragma unroll
    for (int i = 0; i < 4; i++) {
        v[i] = row[tid + i * 256];
        mx = fmaxf(mx, v[i]);
    }
    __shared__ float red[8];
    #pragma unroll
    for (int off = 16; off > 0; off >>= 1)
        mx = fmaxf(mx, __shfl_down_sync(0xffffffffu, mx, off));
    if (lane == 0) red[warp] = mx;
    __syncthreads();
    if (tid == 0) {
        float t = red[0];
        #pragma unroll
        for (int i = 1; i < 8; i++) t = fmaxf(t, red[i]);
        red[0] = t;
    }
    __syncthreads();
    mx = red[0];

    float sum = 0.f;
    #pragma unroll
    for (int i = 0; i < 4; i++) {
        v[i] = expf(v[i] - mx);
        sum += v[i];
    }
    __shared__ float red2[8];
    #pragma unroll
    for (int off = 16; off > 0; off >>= 1)
        sum += __shfl_down_sync(0xffffffffu, sum, off);
    if (lane == 0) red2[warp] = sum;
    __syncthreads();
    if (tid == 0) {
        float t = 0.f;
        #pragma unroll
        for (int i = 0; i < 8; i++) t += red2[i];
        red2[0] = 1.f / t;
    }
    __syncthreads();
    float inv = red2[0];
    #pragma unroll
    for (int i = 0; i < 4; i++)
        row[tid + i * 256] = v[i] * inv;
}

// ---------------------------------------------------------------------------
// Kernel 3: read_output[b][w] = sum_r (sum_m rw[b][r][m]) * rv[b][r][w]
//   grid = B, block = 256
// ---------------------------------------------------------------------------
__global__ void __launch_bounds__(256)
k_read(const float* __restrict__ read_weights,
       const float* __restrict__ read_vectors,
       float* __restrict__ out) {
    const int b = blockIdx.x;
    const int tid = threadIdx.x;
    const int lane = tid & 31, warp = tid >> 5;

    float p[NR_];
    #pragma unroll
    for (int r = 0; r < NR_; r++) {
        float s = 0.f;
        for (int m = tid; m < M_; m += 256)
            s += read_weights[(b * NR_ + r) * M_ + m];
        p[r] = s;
    }
    __shared__ float red[8][NR_];
    __shared__ float sr[NR_];
    #pragma unroll
    for (int r = 0; r < NR_; r++) {
        float s = p[r];
        #pragma unroll
        for (int off = 16; off > 0; off >>= 1)
            s += __shfl_down_sync(0xffffffffu, s, off);
        if (lane == 0) red[warp][r] = s;
    }
    __syncthreads();
    if (tid < NR_) {
        float s = 0.f;
        #pragma unroll
        for (int w8 = 0; w8 < 8; w8++) s += red[w8][tid];
        sr[tid] = s;
    }
    __syncthreads();

    float o = 0.f;
    #pragma unroll
    for (int r = 0; r < NR_; r++)
        o += sr[r] * read_vectors[(b * NR_ + r) * W_ + tid];
    out[O_READ + b * W_ + tid] = o;
}

// ---------------------------------------------------------------------------
extern "C" void kernel_launch(void* const* d_in, const int* in_sizes, int n_in,
                              void* d_out, int out_size) {
    const float* memory        = (const float*)d_in[0];
    const float* keys          = (const float*)d_in[1];
    const float* strengths     = (const float*)d_in[2];
    const float* write_weights = (const float*)d_in[3];
    const float* free_gate     = (const float*)d_in[4];
    const float* read_weights  = (const float*)d_in[5];
    const float* prev_link     = (const float*)d_in[6];
    // d_in[7] = prev_precedence_weights (unused: precedence := write_weights)
    const float* prev_usage    = (const float*)d_in[8];
    const float* erase_vectors = (const float*)d_in[9];
    const float* write_vectors = (const float*)d_in[10];
    const float* read_vectors  = (const float*)d_in[11];
    float* out = (float*)d_out;

    // The big passthroughs: link (134 MB) and precedence (= write_weights)
    cudaMemcpyAsync(out + O_LINK, prev_link,
                    (size_t)B_ * NW_ * M_ * M_ * sizeof(float),
                    cudaMemcpyDeviceToDevice, 0);
    cudaMemcpyAsync(out + O_PREC, write_weights,
                    (size_t)B_ * NW_ * M_ * sizeof(float),
                    cudaMemcpyDeviceToDevice, 0);

    k_keyprep<<<B_ * H_, 256>>>(keys, strengths);
    dim3 grid(M_, B_);
    k_fused<<<grid, 256>>>(memory, keys, write_weights, free_gate,
                           read_weights, prev_usage, erase_vectors,
                           write_vectors, out);
    k_softmax<<<B_ * H_, 256>>>(out);
    k_read<<<B_, 256>>>(read_weights, read_vectors, out);
}

// round 6
// speedup vs baseline: 1.0118x; 1.0118x over previous
#include <cuda_runtime.h>
#include <math.h>

// Shapes (fixed by the problem)
#define B_  16
#define M_  1024
#define W_  256
#define H_  8
#define NW_ 2
#define NR_ 4
#define EPS 1e-6f

// Output layout: concatenation of the 6 returned tensors (float32)
#define O_UPD   0                               // [B,M,W]   4,194,304
#define O_COS   (O_UPD + B_*M_*W_)              // [B,H,M]     131,072
#define O_LINK  (O_COS + B_*H_*M_)              // [B,NW,M,M] 33,554,432
#define O_PREC  (O_LINK + B_*NW_*M_*M_)         // [B,NW,M]     32,768
#define O_USE   (O_PREC + B_*NW_*M_)            // [B,M]        16,384
#define O_READ  (O_USE + B_*M_)                 // [B,W]         4,096

// memory-row norms, produced by k_main, consumed by k_epi
__device__ float g_memnorm[B_ * M_];

// ---------------------------------------------------------------------------
// Kernel 1 — the single big pass. One block per (b,m): grid (M, B), block 256.
//  * 8 key dots + ||mem_row||^2  (raw dots -> cos region; norm -> g_memnorm)
//  * erase/write -> updated_memory
//  * usage (thread 0)
//  * folded link copy (512 float4 per block) and precedence copy
// ---------------------------------------------------------------------------
__global__ void __launch_bounds__(256)
k_main(const float* __restrict__ memory,
       const float* __restrict__ keys,
       const float* __restrict__ write_weights,
       const float* __restrict__ free_gate,
       const float* __restrict__ read_weights,
       const float* __restrict__ prev_usage,
       const float* __restrict__ erase_vectors,
       const float* __restrict__ write_vectors,
       const float4* __restrict__ link4,
       float* __restrict__ out) {
    const int m   = blockIdx.x;
    const int b   = blockIdx.y;
    const int tid = threadIdx.x;        // w index
    const int lane = tid & 31, warp = tid >> 5;
    const int flat = b * M_ + m;        // 0 .. 16383

    // ---- bulk link copy: 512 float4 per block, contiguous, fully coalesced
    {
        float4* dst4 = (float4*)(out + O_LINK);
        const long base = (long)flat * 512 + tid;
        float4 a = link4[base];
        float4 c = link4[base + 256];
        dst4[base]       = a;
        dst4[base + 256] = c;
    }
    // ---- precedence copy (first 32 blocks cover all 8192 float4)
    if (flat < 32) {
        ((float4*)(out + O_PREC))[flat * 256 + tid] =
            ((const float4*)write_weights)[flat * 256 + tid];
    }

    // ---- stage keys for this batch (L2-hot)
    __shared__ float skey[H_][W_];
    __shared__ float red[8][9];
    #pragma unroll
    for (int h = 0; h < H_; h++)
        skey[h][tid] = keys[(b * H_ + h) * W_ + tid];
    __syncthreads();

    const float mv = memory[(long)flat * W_ + tid];

    float acc[9];
    acc[8] = mv * mv;
    #pragma unroll
    for (int h = 0; h < H_; h++) acc[h] = mv * skey[h][tid];

    #pragma unroll
    for (int i = 0; i < 9; i++) {
        float s = acc[i];
        #pragma unroll
        for (int off = 16; off > 0; off >>= 1)
            s += __shfl_down_sync(0xffffffffu, s, off);
        if (lane == 0) red[warp][i] = s;
    }
    __syncthreads();
    if (tid < 9) {
        float s = 0.f;
        #pragma unroll
        for (int w8 = 0; w8 < 8; w8++) s += red[w8][tid];
        if (tid < 8)
            out[O_COS + (b * H_ + tid) * M_ + m] = s;          // raw dot
        else
            g_memnorm[flat] = sqrtf(s + EPS);                  // ||mem_row||
    }

    // ---- erase / write
    const float ww0 = write_weights[(b * NW_ + 0) * M_ + m];
    const float ww1 = write_weights[(b * NW_ + 1) * M_ + m];
    float e = ww0 * erase_vectors[(b * NW_ + 0) * W_ + tid]
            + ww1 * erase_vectors[(b * NW_ + 1) * W_ + tid];
    e = fminf(fmaxf(e, 0.f), 1.f);
    float wr = ww0 * write_vectors[(b * NW_ + 0) * W_ + tid]
             + ww1 * write_vectors[(b * NW_ + 1) * W_ + tid];
    out[O_UPD + (long)flat * W_ + tid] = mv * (1.f - e) + wr;

    // ---- usage
    if (tid == 0) {
        float u = prev_usage[flat] + ww0 + ww1;
        #pragma unroll
        for (int r = 0; r < NR_; r++)
            u -= read_weights[(b * NR_ + r) * M_ + m] * free_gate[b * NR_ + r];
        out[O_USE + flat] = fminf(fmaxf(u, 0.f), 1.f);
    }
}

// ---------------------------------------------------------------------------
// Kernel 2 — epilogue. grid = 144, block = 256.
//   blocks 0..127  : (b,h) — key norm + softplus + normalize + softmax over M
//   blocks 128..143: per-b read_output
// ---------------------------------------------------------------------------
__global__ void __launch_bounds__(256)
k_epi(const float* __restrict__ keys,
      const float* __restrict__ strengths,
      const float* __restrict__ read_weights,
      const float* __restrict__ read_vectors,
      float* __restrict__ out) {
    const int tid = threadIdx.x;
    const int lane = tid & 31, warp = tid >> 5;
    __shared__ float red[8];
    __shared__ float bc[2];                 // broadcast slots

    if (blockIdx.x < 128) {
        // ---------------- softmax over M for one (b,h) ----------------
        const int bh = blockIdx.x;
        const int b  = bh >> 3;
        float* row = out + O_COS + (long)bh * M_;

        // key L2 norm (reduce 256 squares)
        {
            float kv = keys[bh * W_ + tid];
            float s = kv * kv;
            #pragma unroll
            for (int off = 16; off > 0; off >>= 1)
                s += __shfl_down_sync(0xffffffffu, s, off);
            if (lane == 0) red[warp] = s;
            __syncthreads();
            if (tid == 0) {
                float t = 0.f;
                #pragma unroll
                for (int i = 0; i < 8; i++) t += red[i];
                bc[0] = sqrtf(t + EPS);
                bc[1] = log1pf(expf(strengths[bh]));   // softplus
            }
            __syncthreads();
        }
        const float knorm = bc[0];
        const float softp = bc[1];

        // load raw dots, normalize+sharpen, then softmax
        float v[4];
        float mx = -INFINITY;
        #pragma unroll
        for (int i = 0; i < 4; i++) {
            int m = tid + i * 256;
            float nd = row[m] / (g_memnorm[b * M_ + m] * knorm + EPS);
            v[i] = nd * softp;
            mx = fmaxf(mx, v[i]);
        }
        #pragma unroll
        for (int off = 16; off > 0; off >>= 1)
            mx = fmaxf(mx, __shfl_down_sync(0xffffffffu, mx, off));
        if (lane == 0) red[warp] = mx;
        __syncthreads();
        if (tid == 0) {
            float t = red[0];
            #pragma unroll
            for (int i = 1; i < 8; i++) t = fmaxf(t, red[i]);
            bc[0] = t;
        }
        __syncthreads();
        mx = bc[0];

        float sum = 0.f;
        #pragma unroll
        for (int i = 0; i < 4; i++) {
            v[i] = expf(v[i] - mx);
            sum += v[i];
        }
        __syncthreads();   // red reuse
        #pragma unroll
        for (int off = 16; off > 0; off >>= 1)
            sum += __shfl_down_sync(0xffffffffu, sum, off);
        if (lane == 0) red[warp] = sum;
        __syncthreads();
        if (tid == 0) {
            float t = 0.f;
            #pragma unroll
            for (int i = 0; i < 8; i++) t += red[i];
            bc[0] = 1.f / t;
        }
        __syncthreads();
        const float inv = bc[0];
        #pragma unroll
        for (int i = 0; i < 4; i++)
            row[tid + i * 256] = v[i] * inv;
    } else {
        // ---------------- read_output for one b ----------------
        const int b = blockIdx.x - 128;
        __shared__ float red4[8][NR_];
        __shared__ float sr[NR_];

        float p[NR_];
        #pragma unroll
        for (int r = 0; r < NR_; r++) {
            float s = 0.f;
            #pragma unroll
            for (int i = 0; i < 4; i++)
                s += read_weights[(b * NR_ + r) * M_ + tid + i * 256];
            p[r] = s;
        }
        #pragma unroll
        for (int r = 0; r < NR_; r++) {
            float s = p[r];
            #pragma unroll
            for (int off = 16; off > 0; off >>= 1)
                s += __shfl_down_sync(0xffffffffu, s, off);
            if (lane == 0) red4[warp][r] = s;
        }
        __syncthreads();
        if (tid < NR_) {
            float s = 0.f;
            #pragma unroll
            for (int w8 = 0; w8 < 8; w8++) s += red4[w8][tid];
            sr[tid] = s;
        }
        __syncthreads();

        float o = 0.f;
        #pragma unroll
        for (int r = 0; r < NR_; r++)
            o += sr[r] * read_vectors[(b * NR_ + r) * W_ + tid];
        out[O_READ + b * W_ + tid] = o;
    }
}

// ---------------------------------------------------------------------------
extern "C" void kernel_launch(void* const* d_in, const int* in_sizes, int n_in,
                              void* d_out, int out_size) {
    const float* memory        = (const float*)d_in[0];
    const float* keys          = (const float*)d_in[1];
    const float* strengths     = (const float*)d_in[2];
    const float* write_weights = (const float*)d_in[3];
    const float* free_gate     = (const float*)d_in[4];
    const float* read_weights  = (const float*)d_in[5];
    const float* prev_link     = (const float*)d_in[6];
    // d_in[7] = prev_precedence_weights (unused: precedence := write_weights)
    const float* prev_usage    = (const float*)d_in[8];
    const float* erase_vectors = (const float*)d_in[9];
    const float* write_vectors = (const float*)d_in[10];
    const float* read_vectors  = (const float*)d_in[11];
    float* out = (float*)d_out;

    dim3 grid(M_, B_);
    k_main<<<grid, 256>>>(memory, keys, write_weights, free_gate,
                          read_weights, prev_usage, erase_vectors,
                          write_vectors, (const float4*)prev_link, out);
    k_epi<<<144, 256>>>(keys, strengths, read_weights, read_vectors, out);
}